// round 4
// baseline (speedup 1.0000x reference)
#include <cuda_runtime.h>
#include <math.h>

#define BATCH   32
#define LAYERS  32
#define DIM     4096
#define SELK    24
#define NCHOICE 9
#define GS_EPS  1e-10f

#define F4_PER_LAYER (DIM / 4)      // 1024 float4 per layer

// Block = one batch x 2 layers. 256 threads x 8 float4 = 2048 float4 = 2 layers.
// All 8 loads issue before any store (MLP=8). No __syncthreads: every warp
// redundantly computes the 9-way Gumbel argmax via shuffles (overlapped with
// the feature-load latency; noise/logits are L1/L2-hot after the first warp).

__global__ void fused_kernel(const float4* __restrict__ feats4,
                             const float*  __restrict__ logits,
                             const float*  __restrict__ noise,
                             float* __restrict__ out) {
    const int b  = blockIdx.y;
    const int lp = blockIdx.x;            // layer pair 0..15 -> layers 2lp, 2lp+1
    const int t  = threadIdx.x;
    const int l0 = lp * 2;

    // ---- feature loads first: 8 independent LDG.128, no idx dependency ----
    const float4* __restrict__ src =
        feats4 + ((size_t)b * LAYERS + l0) * F4_PER_LAYER;
    float4 v0 = src[t];
    float4 v1 = src[t + 256];
    float4 v2 = src[t + 512];
    float4 v3 = src[t + 768];
    float4 v4 = src[t + 1024];
    float4 v5 = src[t + 1280];
    float4 v6 = src[t + 1536];
    float4 v7 = src[t + 1792];

    // ---- per-warp Gumbel argmax (lanes 0-8 contribute), overlapped ----
    const int lane = t & 31;
    float v  = -INFINITY;
    int   bc = lane;
    if (lane < NCHOICE) {
        float u = noise[b * NCHOICE + lane];
        float g = -logf(-logf(u + GS_EPS) + GS_EPS);
        v = logits[lane] + g;             // tau=1; softmax monotone -> same argmax
    }
    #pragma unroll
    for (int off = 16; off; off >>= 1) {
        float ov = __shfl_down_sync(0xffffffffu, v,  off);
        int   oc = __shfl_down_sync(0xffffffffu, bc, off);
        if (ov > v || (ov == v && oc < bc)) { v = ov; bc = oc; }  // first-max wins
    }
    const int idx = __shfl_sync(0xffffffffu, bc, 0);

    // one-hot selection_probs tail: one warp per batch
    if (lp == 0 && t < NCHOICE) {
        out[(size_t)BATCH * SELK * DIM + b * NCHOICE + t] =
            (t == idx) ? 1.0f : 0.0f;
    }

    // ---- block-uniform predicated stores per layer ----
    float4* __restrict__ outb = (float4*)out + (size_t)b * SELK * F4_PER_LAYER;

    const unsigned rel0 = (unsigned)(l0 - idx);
    if (rel0 < SELK) {
        float4* __restrict__ dst = outb + (size_t)rel0 * F4_PER_LAYER;
        dst[t]       = v0;
        dst[t + 256] = v1;
        dst[t + 512] = v2;
        dst[t + 768] = v3;
    }
    const unsigned rel1 = (unsigned)(l0 + 1 - idx);
    if (rel1 < SELK) {
        float4* __restrict__ dst = outb + (size_t)rel1 * F4_PER_LAYER;
        dst[t]       = v4;
        dst[t + 256] = v5;
        dst[t + 512] = v6;
        dst[t + 768] = v7;
    }
}

extern "C" void kernel_launch(void* const* d_in, const int* in_sizes, int n_in,
                              void* d_out, int out_size) {
    const float* feats  = (const float*)d_in[0];
    const float* logits = (const float*)d_in[1];
    const float* noise  = (const float*)d_in[2];
    float*       out    = (float*)d_out;

    dim3 grid(LAYERS / 2, BATCH);         // (16, 32) = 512 blocks
    fused_kernel<<<grid, 256>>>((const float4*)feats, logits, noise, out);
}